// round 17
// baseline (speedup 1.0000x reference)
#include <cuda_runtime.h>
#include <cstdint>

#define E_DIM 128
#define B_SZ  1024
#define T_SZ  200
#define NTHR  256

#define ROW_A 272            // 128 fp16 padded to 272B (ldmatrix conflict-free)

#define OFF_A    0           // 208*272 = 56576
#define OFF_STG  56576       // 4 x 12800 B staging (25 rows each)
#define STG_SZ   12800
#define CH_F4    800         // float4 per 25-row chunk
#define OFF_RED  107776      // 416 f32 = 1664
#define SMEM_BYTES 109440    // x2 CTAs/SM = 218880 <= 228KB

// device scratch
__device__ float g_WkF[8192];           // fragment-ordered W0b-W0c
__device__ float g_WdF[8192];           // fragment-ordered W0d
__device__ float g_WqT[128 * 64];       // [e*64+h] W0a+W0c
__device__ uint4 g_Wbf[B_SZ * 1024];    // per-batch B fragments [b][ng][nt][k2][lane]
__device__ float g_qA[B_SZ * 64];       // b0 folded in

__device__ __forceinline__ uint32_t pkf16(float lo, float hi) {
    uint32_t r;
    asm("cvt.rn.f16x2.f32 %0, %1, %2;" : "=r"(r) : "f"(hi), "f"(lo));
    return r;
}
__device__ __forceinline__ uint32_t smem_u32(const void* p) {
    uint32_t a;
    asm("{ .reg .u64 t; cvta.to.shared.u64 t, %1; cvt.u32.u64 %0, t; }" : "=r"(a) : "l"(p));
    return a;
}
__device__ __forceinline__ void cp16(uint32_t dst, const float4* src) {
    asm volatile("cp.async.cg.shared.global [%0], [%1], 16;"
                 :: "r"(dst), "l"(__cvta_generic_to_global(src)) : "memory");
}
#define CP_COMMIT() asm volatile("cp.async.commit_group;" ::: "memory")
#define CP_WAIT(n)  asm volatile("cp.async.wait_group %0;" :: "n"(n) : "memory")

#define LDSM4(r, addr) \
    asm volatile("ldmatrix.sync.aligned.m8n8.x4.shared.b16 {%0,%1,%2,%3}, [%4];" \
        : "=r"((r)[0]), "=r"((r)[1]), "=r"((r)[2]), "=r"((r)[3]) : "r"(addr))

__device__ __forceinline__ void mma_f16(float* c, const uint32_t* a, uint32_t b0, uint32_t b1) {
    asm volatile("mma.sync.aligned.m16n8k16.row.col.f32.f16.f16.f32 "
        "{%0,%1,%2,%3}, {%4,%5,%6,%7}, {%8,%9}, {%0,%1,%2,%3};"
        : "+f"(c[0]), "+f"(c[1]), "+f"(c[2]), "+f"(c[3])
        : "r"(a[0]), "r"(a[1]), "r"(a[2]), "r"(a[3]), "r"(b0), "r"(b1));
}

// ---- prep0: fold W0 into fragment-ordered tables (verbatim R14) ----
__global__ void prep0(const float* __restrict__ W0) {
    int idx = blockIdx.x * blockDim.x + threadIdx.x;
    if (idx < 8192) {
        int id = idx >> 3, u = idx & 7;
        int lane = id & 31, k2 = (id >> 5) & 3, nt = (id >> 7) & 3, ng = id >> 9;
        int h = ng * 32 + nt * 8 + (lane >> 2);
        int e = 32 * k2 + 2 * (lane & 3) + ((u >> 1) << 3) + (u & 1);
        g_WkF[idx] = __ldg(&W0[(128 + e) * 64 + h]) - __ldg(&W0[(256 + e) * 64 + h]);
        g_WdF[idx] = __ldg(&W0[(384 + e) * 64 + h]);
    } else {
        int i = idx - 8192;
        int h = i & 63, e = i >> 6;
        g_WqT[e * 64 + h] = __ldg(&W0[e * 64 + h]) + __ldg(&W0[(256 + e) * 64 + h]);
    }
}

// ---- prep1: per-batch B fragments + qA (verbatim R14) ----
__global__ void __launch_bounds__(256, 4) prep1(
    const float* __restrict__ query, const float* __restrict__ b0)
{
    __shared__ float sq[128];
    __shared__ float sr[256];
    const int tid = threadIdx.x;
    const int b = blockIdx.x;

    if (tid < 128) sq[tid] = __ldg(&query[(size_t)b * E_DIM + tid]);
    __syncthreads();

    #pragma unroll
    for (int j = 0; j < 4; j++) {
        int id = j * 256 + tid;
        int lane = id & 31, k2 = (id >> 5) & 3;
        int e0 = 32 * k2 + 2 * (lane & 3);
        float4 wk0 = __ldg((const float4*)(g_WkF + id * 8));
        float4 wk1 = __ldg((const float4*)(g_WkF + id * 8 + 4));
        float4 wd0 = __ldg((const float4*)(g_WdF + id * 8));
        float4 wd1 = __ldg((const float4*)(g_WdF + id * 8 + 4));
        uint4 v;
        v.x = pkf16(fmaf(sq[e0],      wd0.x, wk0.x), fmaf(sq[e0 + 1],  wd0.y, wk0.y));
        v.y = pkf16(fmaf(sq[e0 + 8],  wd0.z, wk0.z), fmaf(sq[e0 + 9],  wd0.w, wk0.w));
        v.z = pkf16(fmaf(sq[e0 + 16], wd1.x, wk1.x), fmaf(sq[e0 + 17], wd1.y, wk1.y));
        v.w = pkf16(fmaf(sq[e0 + 24], wd1.z, wk1.z), fmaf(sq[e0 + 25], wd1.w, wk1.w));
        g_Wbf[(size_t)b * 1024 + id] = v;
    }
    {
        int h6 = tid & 63, grp = tid >> 6;
        float p = 0.f;
        #pragma unroll 8
        for (int i = 0; i < 32; i++) {
            int e = grp * 32 + i;
            p += sq[e] * __ldg(&g_WqT[e * 64 + h6]);
        }
        sr[grp * 64 + h6] = p;
    }
    __syncthreads();
    if (tid < 64)
        g_qA[(size_t)b * 64 + tid] = __ldg(&b0[tid]) + sr[tid] + sr[64 + tid]
                                   + sr[128 + tid] + sr[192 + tid];
}

// ---- main: one batch per CTA (R11-verified shape), 4-deep cp.async pipeline ----
__global__ void __launch_bounds__(NTHR, 2) lau_main(
    const float* __restrict__ keys, const float* __restrict__ W1,
    const float* __restrict__ b1,   float* __restrict__ out)
{
    extern __shared__ __align__(1024) char sm[];
    const uint32_t smb = smem_u32(sm);
    const int tid = threadIdx.x;
    const int b = blockIdx.x;
    const int w = tid >> 5, lane = tid & 31;
    const int mg = w >> 1, ng = w & 1;          // 4 m-groups x 2 n-groups
    const int lq = lane >> 2, lr = lane & 3;
    float* sRed = (float*)(sm + OFF_RED);

    const float4* k4 = (const float4*)(keys + (size_t)b * T_SZ * E_DIM);

    // kick chunks 0..3 (25 rows = 800 float4 each) into the 4 buffers
    #pragma unroll
    for (int c = 0; c < 4; c++) {
        const float4* src = k4 + c * CH_F4;
        uint32_t stg = smb + OFF_STG + c * STG_SZ;
        #pragma unroll
        for (int i = 0; i < 4; i++) {
            int idx = i * NTHR + tid;
            if (idx < CH_F4) cp16(stg + idx * 16, src + idx);
        }
        CP_COMMIT();
    }

    // zero A tail rows 200-207
    if (tid < 136)
        *(uint4*)(sm + OFF_A + 200 * ROW_A + tid * 16) = make_uint4(0, 0, 0, 0);

    // B fragments (coalesced L2 reads; overlap the cp.async DRAM wait)
    uint32_t bf[4][8][2];
    {
        const uint4* wb4 = g_Wbf + ((size_t)b * 2 + ng) * 512 + lane;
        #pragma unroll
        for (int nt = 0; nt < 4; nt++)
            #pragma unroll
            for (int k2 = 0; k2 < 4; k2++) {
                uint4 v = __ldg(&wb4[nt * 128 + k2 * 32]);
                bf[nt][2 * k2][0] = v.x;     bf[nt][2 * k2][1] = v.y;
                bf[nt][2 * k2 + 1][0] = v.z; bf[nt][2 * k2 + 1][1] = v.w;
            }
    }
    float qa[8], w1v[8];
    #pragma unroll
    for (int nt = 0; nt < 4; nt++) {
        #pragma unroll
        for (int u = 0; u < 2; u++) {
            int c = ng * 32 + nt * 8 + 2 * lr + u;
            qa[2 * nt + u]  = __ldg(&g_qA[(size_t)b * 64 + c]);
            w1v[2 * nt + u] = __ldg(&W1[c]);
        }
    }
    const float b1v = __ldg(b1);

    // 8 convert phases; self-mapped (thread converts what it cp.async'd) -> no barriers
    #pragma unroll
    for (int c = 0; c < 8; c++) {
        CP_WAIT(3);
        const float4* s4 = (const float4*)(sm + OFF_STG + (c & 3) * STG_SZ);
        float4 v[4];
        #pragma unroll
        for (int i = 0; i < 4; i++) {
            int idx = i * NTHR + tid;
            if (idx < CH_F4) v[i] = s4[idx];
        }
        if (c + 4 < 8) {                        // refill this buffer with chunk c+4
            const float4* src = k4 + (c + 4) * CH_F4;
            uint32_t stg = smb + OFF_STG + (c & 3) * STG_SZ;
            #pragma unroll
            for (int i = 0; i < 4; i++) {
                int idx = i * NTHR + tid;
                if (idx < CH_F4) cp16(stg + idx * 16, src + idx);
            }
        }
        CP_COMMIT();                            // uniform group count
        #pragma unroll
        for (int i = 0; i < 4; i++) {
            int idx = i * NTHR + tid;
            if (idx < CH_F4) {
                int row = c * 25 + (idx >> 5), cc = idx & 31;
                *(uint2*)(sm + OFF_A + row * ROW_A + cc * 8) =
                    make_uint2(pkf16(v[i].x, v[i].y), pkf16(v[i].z, v[i].w));
            }
        }
    }
    __syncthreads();                            // (S1) A ready

    // per-tile mma + inline epilogue (acc per tile: no spills)
    const uint32_t aB = smb + OFF_A + (lane & 15) * ROW_A + (lane >> 4) * 16;
    #pragma unroll
    for (int i = 0; i < 4; i++) {
        int t = mg + 4 * i;
        if (t < 13) {
            float acc[4][4];
            #pragma unroll
            for (int nt = 0; nt < 4; nt++)
                #pragma unroll
                for (int u = 0; u < 4; u++) acc[nt][u] = 0.f;
            #pragma unroll
            for (int ks = 0; ks < 8; ks++) {
                uint32_t a[4];
                LDSM4(a, aB + t * (16 * ROW_A) + ks * 32);
                #pragma unroll
                for (int nt = 0; nt < 4; nt++)
                    mma_f16(acc[nt], a, bf[nt][ks][0], bf[nt][ks][1]);
            }
            float p0 = 0.f, p1 = 0.f;
            #pragma unroll
            for (int nt = 0; nt < 4; nt++) {
                p0 += fmaxf(acc[nt][0] + qa[2 * nt],     0.f) * w1v[2 * nt]
                    + fmaxf(acc[nt][1] + qa[2 * nt + 1], 0.f) * w1v[2 * nt + 1];
                p1 += fmaxf(acc[nt][2] + qa[2 * nt],     0.f) * w1v[2 * nt]
                    + fmaxf(acc[nt][3] + qa[2 * nt + 1], 0.f) * w1v[2 * nt + 1];
            }
            p0 += __shfl_xor_sync(0xffffffffu, p0, 1);
            p0 += __shfl_xor_sync(0xffffffffu, p0, 2);
            p1 += __shfl_xor_sync(0xffffffffu, p1, 1);
            p1 += __shfl_xor_sync(0xffffffffu, p1, 2);
            if (lr == 0) {
                sRed[ng * 208 + t * 16 + lq]     = p0;
                sRed[ng * 208 + t * 16 + lq + 8] = p1;
            }
        }
    }
    __syncthreads();                            // (S2) sRed ready
    if (tid < T_SZ)
        out[(size_t)b * T_SZ + tid] = sRed[tid] + sRed[208 + tid] + b1v;
}

extern "C" void kernel_launch(void* const* d_in, const int* in_sizes, int n_in,
                              void* d_out, int out_size) {
    const float* query = (const float*)d_in[0];
    const float* keys  = (const float*)d_in[1];
    const float* W0    = (const float*)d_in[2];
    const float* b0    = (const float*)d_in[3];
    const float* W1    = (const float*)d_in[4];
    const float* b1    = (const float*)d_in[5];
    float* out = (float*)d_out;

    cudaFuncSetAttribute(lau_main, cudaFuncAttributeMaxDynamicSharedMemorySize, SMEM_BYTES);

    prep0<<<64, 256>>>(W0);
    prep1<<<B_SZ, 256>>>(query, b0);
    lau_main<<<B_SZ, NTHR, SMEM_BYTES>>>(keys, W1, b1, out);
}